// round 9
// baseline (speedup 1.0000x reference)
#include <cuda_runtime.h>
#include <math.h>

#define BB 16
#define CC 64
#define NN 1024
#define NH 4
#define FF 15
#define FH 60
#define KK 9
#define ALPHA 0.2f

typedef unsigned long long u64;

// ---------------- scratch (device globals; no allocation) ----------------
__device__ __align__(16) float g_h[BB*CC*NN];      // [b][c][n]
__device__ __align__(16) float g_nsq[BB*NN];       // -0.5*||h_n||^2
__device__ __align__(16) int   g_idx[BB*NN*KK];
__device__ __align__(16) u64   g_part[BB*NN*8*9];  // per-chunk sorted top-9 keys
__device__ __align__(16) float g_Wh[BB*NN*FH];     // [b][n][60] (head-major 4x15)
__device__ __align__(16) float g_f1[BB*NN*NH];
__device__ __align__(16) float g_f2[BB*NN*NH];
__device__ __align__(16) float g_den[BB*NN*NH];
__device__ __align__(16) float g_ew[BB*NN*KK*NH];  // cached exp per edge per head
__device__ __align__(16) float g_hcat[BB*NN*FH];
__device__ __align__(16) float g_Who[BB*NN*CC];    // [b][n][64]
__device__ __align__(16) float g_f1o[BB*NN];
__device__ __align__(16) float g_f2o[BB*NN];
__device__ __align__(16) float g_deno[BB*NN];
__device__ __align__(16) float g_ewo[BB*NN*KK];

__global__ void k_dummy() {}

// ---------------- K1: L2 normalize over C (2 threads per node) ----------------
__global__ void k_norm(const float* __restrict__ x) {
    int tid = blockIdx.x * 256 + threadIdx.x;        // [0, 2*B*N)
    int node = tid >> 1, half = tid & 1;
    int b = node >> 10, n = node & 1023;
    const float* xp = x + (size_t)b * CC * NN + half * 32 * NN + n;
    float v[32];
    float s = 0.f;
#pragma unroll
    for (int c = 0; c < 32; c++) { v[c] = xp[c * NN]; s += v[c] * v[c]; }
    s += __shfl_xor_sync(0xFFFFFFFFu, s, 1);
    float nrm = fmaxf(sqrtf(s), 1e-12f);
    float r = 1.0f / nrm;
    float* hp = g_h + (size_t)b * CC * NN + half * 32 * NN + n;
    float s2 = 0.f;
#pragma unroll
    for (int c = 0; c < 32; c++) {
        float w = v[c] * r;
        hp[c * NN] = w;
        s2 += w * w;
    }
    s2 += __shfl_xor_sync(0xFFFFFFFFu, s2, 1);
    if (half == 0) g_nsq[node] = -0.5f * s2;
}

// ---------------- K2: one 128x128 score chunk per block + partial top-9 ----------------
// score_ij = dot(h_i,h_j) - 0.5*sq_j (channel 65 folds -0.5*sq_j).
// grid (8 i-tiles, 8 j-chunks, 16 b) = 1024 blocks, 2 blocks/SM.
// Thread tile 4i x 16j, f32x2 lanes paired over j (b pairs native; 4 a-splats/c).
// Accumulators stored to Ds directly as u64 (no unpack) -> scan j-contiguous.
#define KCH 65
#define DSTR 68
extern __shared__ float smem_g[];
__global__ __launch_bounds__(256, 2) void k_gramtop(const float* __restrict__ Wheads,
                                                    const float* __restrict__ aheads) {
    float* As = smem_g;                           // [65][128] 33.3KB
    float* Bs = smem_g + KCH * 128;               // [65][128] 33.3KB
    float* Ds = smem_g + 2 * KCH * 128;           // [128][68] 34.8KB (64-col phases)
    u64*   keys = (u64*)Ds;                       // 256*9 u64 = 18KB (reuse)

    int b = blockIdx.z;
    int i0 = blockIdx.x * 128;
    int jc = blockIdx.y;
    int j0 = jc * 128;
    int t = threadIdx.x;
    const float* hb = g_h + (size_t)b * CC * NN;
    const float* nsqb = g_nsq + b * NN;

    // load As (64 channels + ones) and Bs (64 channels + nsq)
#pragma unroll
    for (int r = 0; r < 8; r++) {
        int lin = t + r * 256;               // [64][32 f4]
        int c = lin >> 5, pos = lin & 31;
        *(float4*)(As + c * 128 + pos * 4) = *(const float4*)(hb + c * NN + i0 + pos * 4);
        *(float4*)(Bs + c * 128 + pos * 4) = *(const float4*)(hb + c * NN + j0 + pos * 4);
    }
    if (t < 128) {
        As[64 * 128 + t] = 1.0f;
        Bs[64 * 128 + t] = nsqb[j0 + t];
    }
    __syncthreads();

    int tx = t & 7, ty = t >> 3;             // j group: tx*16, i group: ty*4
    const float* ap = As + ty * 4;
    const float* bp = Bs + tx * 16;
    u64 acc[4][8];
#pragma unroll
    for (int i = 0; i < 4; i++)
#pragma unroll
        for (int j = 0; j < 8; j++) acc[i][j] = 0ull;

#pragma unroll 13
    for (int c = 0; c < KCH; c++) {
        float4 av = *(const float4*)(ap + c * 128);
        ulonglong2 b01 = *(const ulonglong2*)(bp + c * 128);
        ulonglong2 b23 = *(const ulonglong2*)(bp + c * 128 + 4);
        ulonglong2 b45 = *(const ulonglong2*)(bp + c * 128 + 8);
        ulonglong2 b67 = *(const ulonglong2*)(bp + c * 128 + 12);
        u64 bb[8] = { b01.x, b01.y, b23.x, b23.y, b45.x, b45.y, b67.x, b67.y };
        u64 as_[4];
        asm("mov.b64 %0, {%1, %1};" : "=l"(as_[0]) : "f"(av.x));
        asm("mov.b64 %0, {%1, %1};" : "=l"(as_[1]) : "f"(av.y));
        asm("mov.b64 %0, {%1, %1};" : "=l"(as_[2]) : "f"(av.z));
        asm("mov.b64 %0, {%1, %1};" : "=l"(as_[3]) : "f"(av.w));
#pragma unroll
        for (int i = 0; i < 4; i++)
#pragma unroll
            for (int j = 0; j < 8; j++)
                asm("fma.rn.f32x2 %0, %1, %2, %0;" : "+l"(acc[i][j]) : "l"(as_[i]), "l"(bb[j]));
    }

    // persistent per-thread top-9 (ascending; [0] = threshold)
    float bS[9]; int bI[9];
#pragma unroll
    for (int q = 0; q < 9; q++) { bS[q] = -1e30f; bI[q] = 0; }
    int myrow = t >> 1, half = t & 1;

    // two 64-col phases: direct u64 store -> quad-max scan
#pragma unroll
    for (int ph = 0; ph < 2; ph++) {
        if ((tx >> 2) == ph) {
            int cx = (tx & 3) * 16;          // float offset within phase
#pragma unroll
            for (int i = 0; i < 4; i++) {
                u64* drow = (u64*)(Ds + (ty * 4 + i) * DSTR + cx);
                ulonglong2 v0; v0.x = acc[i][0]; v0.y = acc[i][1];
                ulonglong2 v1; v1.x = acc[i][2]; v1.y = acc[i][3];
                ulonglong2 v2; v2.x = acc[i][4]; v2.y = acc[i][5];
                ulonglong2 v3; v3.x = acc[i][6]; v3.y = acc[i][7];
                *(ulonglong2*)(drow)     = v0;
                *(ulonglong2*)(drow + 2) = v1;
                *(ulonglong2*)(drow + 4) = v2;
                *(ulonglong2*)(drow + 6) = v3;
            }
        }
        __syncthreads();
        // scan: 2 threads/row, 32 contiguous cols each, quad-max prefilter
        const float* dr = Ds + myrow * DSTR + half * 32;
        int jbase = j0 + ph * 64 + half * 32;
        float th = bS[0];
#pragma unroll
        for (int m = 0; m < 8; m++) {
            float4 v = *(const float4*)(dr + 4 * m);
            float mx = fmaxf(fmaxf(v.x, v.y), fmaxf(v.z, v.w));
            if (mx > th) {
                float vv[4] = { v.x, v.y, v.z, v.w };
#pragma unroll
                for (int q = 0; q < 4; q++) {
                    if (vv[q] > th) {
                        bS[0] = vv[q]; bI[0] = jbase + 4 * m + q;
#pragma unroll
                        for (int s = 0; s < 8; s++) {
                            if (bS[s] > bS[s + 1]) {
                                float ts = bS[s]; bS[s] = bS[s + 1]; bS[s + 1] = ts;
                                int   ti = bI[s]; bI[s] = bI[s + 1]; bI[s + 1] = ti;
                            }
                        }
                        th = bS[0];
                    }
                }
            }
        }
        __syncthreads();
    }

    // dump per-thread lists as u64 keys (bigger = better, tie -> smaller j)
#pragma unroll
    for (int q = 0; q < 9; q++) {
        unsigned u = __float_as_uint(bS[q]);
        u = (u & 0x80000000u) ? ~u : (u | 0x80000000u);
        keys[t * 9 + q] = ((u64)u << 32) | (unsigned)(1023 - bI[q]);
    }
    __syncthreads();
    if (t < 128) {
        const u64* L0 = keys + (size_t)(2 * t) * 9;
        const u64* L1 = keys + (size_t)(2 * t + 1) * 9;
        int p0 = 8, p1 = 8;
        u64* op = g_part + ((size_t)(b * NN + i0 + t) * 8 + jc) * 9;
#pragma unroll
        for (int r = 0; r < 9; r++) {
            u64 v0 = L0[p0], v1 = L1[p1];
            bool a = v0 > v1;
            op[r] = a ? v0 : v1;
            if (a) p0--; else p1--;
        }
    }

    // ---- fused k3 epilogue (jc==0 blocks only): Wh, f1/f2, zero den ----
    if (jc != 0) return;
    __syncthreads();
    float* Wc  = Bs;             // [c][h*15+f]  64*60
    float* as2 = Bs + 64 * FH;   // 120
    for (int idx = t; idx < NH * CC * FF; idx += 256) {
        int h = idx / (CC * FF); int rem = idx % (CC * FF);
        int c = rem / FF; int f = rem % FF;
        Wc[c * FH + h * FF + f] = Wheads[idx];
    }
    if (t < NH * 2 * FF) as2[t] = aheads[t];
    __syncthreads();
#pragma unroll
    for (int p = 0; p < 2; p++) {
        int idx = t + p * 256;               // 0..511 = 128 nodes x 4 heads
        int node = idx >> 2, h = idx & 3;
        size_t row = (size_t)b * NN + i0 + node;
        float acc2[FF];
#pragma unroll
        for (int f = 0; f < FF; f++) acc2[f] = 0.f;
#pragma unroll 8
        for (int c = 0; c < CC; c++) {
            float hc = As[c * 128 + node];
#pragma unroll
            for (int f = 0; f < FF; f++) acc2[f] = fmaf(hc, Wc[c * FH + h * FF + f], acc2[f]);
        }
        float* wout = g_Wh + row * FH + h * FF;
#pragma unroll
        for (int f = 0; f < FF; f++) wout[f] = acc2[f];
        float f1 = 0.f, f2 = 0.f;
#pragma unroll
        for (int f = 0; f < FF; f++) {
            f1 = fmaf(acc2[f], as2[h * 2 * FF + f], f1);
            f2 = fmaf(acc2[f], as2[h * 2 * FF + FF + f], f2);
        }
        g_f1[row * NH + h] = f1;
        g_f2[row * NH + h] = f2;
        g_den[row * NH + h] = 0.f;
    }
}

// ---------------- K2b: 8-way merge of sorted chunk lists -> g_idx ----------------
__global__ void k_mergetop() {
    int row = blockIdx.x * 256 + threadIdx.x;        // [0, B*N)
    const u64* L = g_part + (size_t)row * 72;
    u64 cur[8]; int p[8];
#pragma unroll
    for (int l = 0; l < 8; l++) { cur[l] = L[l * 9]; p[l] = 1; }
    int* op = g_idx + (size_t)row * 9;
#pragma unroll
    for (int r = 0; r < 9; r++) {
        u64 m = cur[0]; int ml = 0;
#pragma unroll
        for (int l = 1; l < 8; l++) if (cur[l] > m) { m = cur[l]; ml = l; }
        op[r] = 1023 - (int)(m & 0xFFFFFFFFull);
        cur[ml] = (p[ml] < 9) ? L[ml * 9 + p[ml]] : 0ull;
        p[ml]++;
    }
}

// ---------------- K4: denominators (heads) + exp cache — edge-parallel ----------------
__global__ void k4() {
    int e = blockIdx.x * 256 + threadIdx.x;          // [0, B*N*K)
    int row = e / 9;
    int bbase = row & ~1023;
    int jr = bbase + g_idx[e];
    float4 f1v = *(const float4*)(g_f1 + (size_t)row * 4);
    float4 f2v = *(const float4*)(g_f2 + (size_t)jr * 4);
    float* dp = g_den + (size_t)jr * 4;
    float e0 = f1v.x + f2v.x; e0 = e0 > 0.f ? e0 : ALPHA * e0;
    float e1 = f1v.y + f2v.y; e1 = e1 > 0.f ? e1 : ALPHA * e1;
    float e2 = f1v.z + f2v.z; e2 = e2 > 0.f ? e2 : ALPHA * e2;
    float e3 = f1v.w + f2v.w; e3 = e3 > 0.f ? e3 : ALPHA * e3;
    float x0 = __expf(e0), x1 = __expf(e1), x2 = __expf(e2), x3 = __expf(e3);
    *(float4*)(g_ew + (size_t)e * 4) = make_float4(x0, x1, x2, x3);
    atomicAdd(dp + 0, x0);
    atomicAdd(dp + 1, x1);
    atomicAdd(dp + 2, x2);
    atomicAdd(dp + 3, x3);
}

// ---------------- K5: head aggregation + ELU -> hcat ----------------
__global__ void k5() {
    __shared__ float ws[4 * KK * NH];
    __shared__ int   js[4 * KK];
    int t = threadIdx.x;                 // 240 = 4 nodes x 60
    int row0 = blockIdx.x * 4;
    int bbase = row0 & ~1023;
    if (t < 4 * KK * NH) {
        int local = t / (KK * NH), rem = t % (KK * NH);
        int k = rem >> 2, h = rem & 3;
        int row = row0 + local;
        int jr = bbase + g_idx[row * 9 + k];
        ws[t] = __fdividef(g_ew[((size_t)row * 9 + k) * 4 + h], g_den[(size_t)jr * 4 + h]);
        if (h == 0) js[local * KK + k] = jr;
    }
    __syncthreads();
    int local = t / FH, c = t % FH;
    int row = row0 + local;
    int h = c / FF;
    float acc = 0.f;
#pragma unroll
    for (int k = 0; k < KK; k++)
        acc = fmaf(ws[(local * KK + k) * 4 + h], g_Wh[(size_t)js[local * KK + k] * FH + c], acc);
    g_hcat[(size_t)row * FH + c] = acc > 0.f ? acc : expm1f(acc);
}

// ---------------- K6: W_out GEMM + f1o/f2o, zero deno ----------------
__global__ __launch_bounds__(256) void k6(const float* __restrict__ Wout,
                                          const float* __restrict__ aout) {
    __shared__ float Hc[64 * 61];        // [node][c]
    __shared__ float Wo[FH * CC];
    __shared__ float av[2 * CC];
    int t = threadIdx.x;
    int b = blockIdx.x >> 4;
    int n0 = (blockIdx.x & 15) * 64;
    for (int idx = t; idx < FH * CC; idx += 256) Wo[idx] = Wout[idx];
    if (t < 2 * CC) av[t] = aout[t];
    for (int idx = t; idx < 64 * FH; idx += 256) {
        int node = idx / FH, c = idx % FH;
        Hc[node * 61 + c] = g_hcat[((size_t)(b * NN + n0 + node)) * FH + c];
    }
    __syncthreads();
    int node = t >> 2, q = t & 3;
    size_t row = (size_t)b * NN + n0 + node;
    float acc[16];
#pragma unroll
    for (int f = 0; f < 16; f++) acc[f] = 0.f;
#pragma unroll 6
    for (int c = 0; c < FH; c++) {
        float hv = Hc[node * 61 + c];
#pragma unroll
        for (int f = 0; f < 16; f++)
            acc[f] = fmaf(hv, Wo[c * CC + q * 16 + f], acc[f]);
    }
    float4* wout4 = (float4*)(g_Who + row * CC + q * 16);
#pragma unroll
    for (int p = 0; p < 4; p++)
        wout4[p] = make_float4(acc[4 * p], acc[4 * p + 1], acc[4 * p + 2], acc[4 * p + 3]);
    float f1 = 0.f, f2 = 0.f;
#pragma unroll
    for (int f = 0; f < 16; f++) {
        f1 = fmaf(acc[f], av[q * 16 + f], f1);
        f2 = fmaf(acc[f], av[CC + q * 16 + f], f2);
    }
#pragma unroll
    for (int off = 1; off < 4; off <<= 1) {
        f1 += __shfl_xor_sync(0xFFFFFFFFu, f1, off);
        f2 += __shfl_xor_sync(0xFFFFFFFFu, f2, off);
    }
    if (q == 0) {
        g_f1o[row] = f1;
        g_f2o[row] = f2;
        g_deno[row] = 0.f;
    }
}

// ---------------- K7: output-layer denominators + exp cache — edge-parallel ----------------
__global__ void k7() {
    int e = blockIdx.x * 256 + threadIdx.x;          // [0, B*N*K)
    int row = e / 9;
    int bbase = row & ~1023;
    int jr = bbase + g_idx[e];
    float ee = g_f1o[row] + g_f2o[jr];
    ee = ee > 0.f ? ee : ALPHA * ee;
    float ex = __expf(ee);
    g_ewo[e] = ex;
    atomicAdd(g_deno + jr, ex);
}

// ---------------- K8: out-aggregate + ELU + LReLU + conv1x1 + BN + residual ----------------
__global__ void k8(const float* __restrict__ x, const float* __restrict__ cw,
                   const float* __restrict__ cb, const float* __restrict__ gamma,
                   const float* __restrict__ beta, float* __restrict__ out) {
    __shared__ float cws[CC * 65];
    __shared__ float ys[32 * 65];
    __shared__ float ws[32 * KK];
    __shared__ int   js[32 * KK];
    int t = threadIdx.x;
    int b = blockIdx.x >> 5;
    int n0 = (blockIdx.x & 31) * 32;
    for (int idx = t; idx < CC * CC; idx += 256) {
        int o = idx >> 6, c = idx & 63;
        cws[o * 65 + c] = cw[idx];
    }
    for (int idx = t; idx < 32 * KK; idx += 256) {
        int node = idx / KK, k = idx % KK;
        int row = b * NN + n0 + node;
        int jr = b * NN + g_idx[row * 9 + k];
        ws[idx] = __fdividef(g_ewo[(size_t)row * 9 + k], g_deno[jr]);
        js[idx] = jr;
    }
    __syncthreads();
#pragma unroll
    for (int p = 0; p < 8; p++) {
        int idx = t + p * 256;
        int node = idx >> 6, c = idx & 63;
        float acc = 0.f;
#pragma unroll
        for (int k = 0; k < KK; k++)
            acc = fmaf(ws[node * KK + k], g_Who[(size_t)js[node * KK + k] * CC + c], acc);
        float e = acc > 0.f ? acc : expm1f(acc);     // ELU
        ys[node * 65 + c] = e > 0.f ? e : 0.01f * e; // LeakyReLU(0.01)
    }
    __syncthreads();
    int node = t & 31, og = t >> 5;
    float bnr = 1.0f / sqrtf(1.0f + 1e-5f);
#pragma unroll
    for (int p = 0; p < 8; p++) {
        int o = og * 8 + p;
        float s = cb[o];
        const float* yr = ys + node * 65;
        const float* cr = cws + o * 65;
#pragma unroll
        for (int c = 0; c < CC; c++) s = fmaf(cr[c], yr[c], s);
        s = s * bnr * gamma[o] + beta[o];
        size_t oidx = ((size_t)(b * CC + o)) * NN + n0 + node;
        out[oidx] = s + x[oidx];
    }
}

// ---------------- launch ----------------
extern "C" void kernel_launch(void* const* d_in, const int* in_sizes, int n_in,
                              void* d_out, int out_size) {
    const float* x      = (const float*)d_in[0];
    const float* Wheads = (const float*)d_in[1];
    const float* aheads = (const float*)d_in[2];
    const float* Wout   = (const float*)d_in[3];
    const float* aout   = (const float*)d_in[4];
    const float* convw  = (const float*)d_in[5];
    const float* convb  = (const float*)d_in[6];
    const float* gamma  = (const float*)d_in[7];
    const float* beta   = (const float*)d_in[8];
    float* out = (float*)d_out;

    const int GT_SMEM = (2 * KCH * 128 + 128 * DSTR) * 4;  // 101376B
    static bool attr_set = false;
    if (!attr_set) {
        cudaFuncSetAttribute(k_gramtop, cudaFuncAttributeMaxDynamicSharedMemorySize, GT_SMEM);
        attr_set = true;
    }

    k_norm<<<2 * BB * NN / 256, 256>>>(x);       // launch 0
    k_dummy<<<1, 32>>>();                        // launch 1
    k_dummy<<<1, 32>>>();                        // launch 2
    k_gramtop<<<dim3(8, 8, BB), 256, GT_SMEM>>>(Wheads, aheads);  // launch 3 (profiled)
    k_mergetop<<<BB * NN / 256, 256>>>();
    k4<<<BB * NN * KK / 256, 256>>>();
    k5<<<BB * NN / 4, 240>>>();
    k6<<<BB * 16, 256>>>(Wout, aout);
    k7<<<BB * NN * KK / 256, 256>>>();
    k8<<<BB * 32, 256>>>(x, convw, convb, gamma, beta, out);
}

// round 10
// speedup vs baseline: 1.4837x; 1.4837x over previous
#include <cuda_runtime.h>
#include <math.h>

#define BB 16
#define CC 64
#define NN 1024
#define NH 4
#define FF 15
#define FH 60
#define KK 9
#define ALPHA 0.2f

typedef unsigned long long u64;

// ---------------- scratch (device globals; no allocation) ----------------
__device__ __align__(16) float g_h[BB*CC*NN];      // [b][c][n]
__device__ __align__(16) float g_nsq[BB*NN];       // -0.5*||h_n||^2
__device__ __align__(16) int   g_idx[BB*NN*KK];
__device__ __align__(16) u64   g_part[BB*NN*8*9];  // per-chunk sorted top-9 keys
__device__ __align__(16) float g_Wh[BB*NN*FH];     // [b][n][60] (head-major 4x15)
__device__ __align__(16) float g_f1[BB*NN*NH];
__device__ __align__(16) float g_f2[BB*NN*NH];
__device__ __align__(16) float g_den[BB*NN*NH];
__device__ __align__(16) float g_ew[BB*NN*KK*NH];  // cached exp per edge per head
__device__ __align__(16) float g_hcat[BB*NN*FH];
__device__ __align__(16) float g_Who[BB*NN*CC];    // [b][n][64]
__device__ __align__(16) float g_f1o[BB*NN];
__device__ __align__(16) float g_f2o[BB*NN];
__device__ __align__(16) float g_deno[BB*NN];
__device__ __align__(16) float g_ewo[BB*NN*KK];

__global__ void k_dummy() {}

// ---------------- K1: L2 normalize over C (2 threads per node) ----------------
__global__ void k_norm(const float* __restrict__ x) {
    int tid = blockIdx.x * 256 + threadIdx.x;        // [0, 2*B*N)
    int node = tid >> 1, half = tid & 1;
    int b = node >> 10, n = node & 1023;
    const float* xp = x + (size_t)b * CC * NN + half * 32 * NN + n;
    float v[32];
    float s = 0.f;
#pragma unroll
    for (int c = 0; c < 32; c++) { v[c] = xp[c * NN]; s += v[c] * v[c]; }
    s += __shfl_xor_sync(0xFFFFFFFFu, s, 1);
    float nrm = fmaxf(sqrtf(s), 1e-12f);
    float r = 1.0f / nrm;
    float* hp = g_h + (size_t)b * CC * NN + half * 32 * NN + n;
    float s2 = 0.f;
#pragma unroll
    for (int c = 0; c < 32; c++) {
        float w = v[c] * r;
        hp[c * NN] = w;
        s2 += w * w;
    }
    s2 += __shfl_xor_sync(0xFFFFFFFFu, s2, 1);
    if (half == 0) g_nsq[node] = -0.5f * s2;
}

// ---------------- K2: symmetric 128x128 dot tiles (upper triangle) + dual top-9 ----------------
// Per unordered tile pair (a,bt): dot computed once; row-scan (score+nsq_j) fills
// slot [i][bt], col-scan (score+nsq_i) fills slot [j][a]. Diagonal: row-scan only.
// grid (36 triangle tiles, 16 b) = 576 blocks, 2 blocks/SM. GEMM = R7 inner loop.
#define DSTR 68
extern __shared__ float smem_g[];
__global__ __launch_bounds__(256, 2) void k_gramtop(const float* __restrict__ Wheads,
                                                    const float* __restrict__ aheads) {
    float* As   = smem_g;                 // [64][128] 32KB
    float* Bs   = smem_g + 8192;          // [64][128] 32KB
    float* Ds   = smem_g + 16384;         // [128][68] 34.8KB (64-col phases)
    float* nsqA = smem_g + 25088;         // [128]
    float* nsqB = smem_g + 25216;         // [128]
    u64* keysR = (u64*)Ds;                // row-dump scratch (Ds free then)
    u64* keysC = (u64*)As;                // col-dump scratch (As free post-GEMM, off-diag only)

    // triangle decode: blockIdx.x in [0,36) -> (a, bt), a <= bt
    int a = 0, rem = blockIdx.x;
    while (rem >= 8 - a) { rem -= 8 - a; a++; }
    int bt = a + rem;
    bool diag = (a == bt);

    int b = blockIdx.y;
    int i0 = a * 128;
    int j0 = bt * 128;
    int t = threadIdx.x;
    const float* hb = g_h + (size_t)b * CC * NN;
    const float* nsqb = g_nsq + b * NN;

#pragma unroll
    for (int r = 0; r < 8; r++) {
        int lin = t + r * 256;               // [64][32 f4]
        int c = lin >> 5, pos = lin & 31;
        *(float4*)(As + c * 128 + pos * 4) = *(const float4*)(hb + c * NN + i0 + pos * 4);
        *(float4*)(Bs + c * 128 + pos * 4) = *(const float4*)(hb + c * NN + j0 + pos * 4);
    }
    if (t < 128) {
        nsqA[t] = nsqb[i0 + t];
        nsqB[t] = nsqb[j0 + t];
    }
    __syncthreads();

    int tx = t & 31, ty = t >> 5;            // j group: tx*4, i group: ty*16
    const float* ap = As + ty * 16;
    const float* bp = Bs + tx * 4;
    u64 acc[8][4];
#pragma unroll
    for (int p = 0; p < 8; p++)
#pragma unroll
        for (int j = 0; j < 4; j++) acc[p][j] = 0ull;

#pragma unroll 4
    for (int c = 0; c < 64; c++) {
        ulonglong2 a01 = *(const ulonglong2*)(ap + c * 128);
        ulonglong2 a23 = *(const ulonglong2*)(ap + c * 128 + 4);
        ulonglong2 a45 = *(const ulonglong2*)(ap + c * 128 + 8);
        ulonglong2 a67 = *(const ulonglong2*)(ap + c * 128 + 12);
        u64 apair[8] = { a01.x, a01.y, a23.x, a23.y, a45.x, a45.y, a67.x, a67.y };
        float4 bv = *(const float4*)(bp + c * 128);
        u64 bs_[4];
        asm("mov.b64 %0, {%1, %1};" : "=l"(bs_[0]) : "f"(bv.x));
        asm("mov.b64 %0, {%1, %1};" : "=l"(bs_[1]) : "f"(bv.y));
        asm("mov.b64 %0, {%1, %1};" : "=l"(bs_[2]) : "f"(bv.z));
        asm("mov.b64 %0, {%1, %1};" : "=l"(bs_[3]) : "f"(bv.w));
#pragma unroll
        for (int p = 0; p < 8; p++)
#pragma unroll
            for (int j = 0; j < 4; j++)
                asm("fma.rn.f32x2 %0, %1, %2, %0;" : "+l"(acc[p][j]) : "l"(apair[p]), "l"(bs_[j]));
    }

    // persistent per-thread ROW top-9 (ascending; [0] = threshold)
    float bS[9]; int bI[9];
#pragma unroll
    for (int q = 0; q < 9; q++) { bS[q] = -1e30f; bI[q] = 0; }
    int myrow = t >> 1, half = t & 1;
    int c2 = t >> 2, qq = t & 3;             // col-scan assignment

    // two 64-col phases
#pragma unroll
    for (int ph = 0; ph < 2; ph++) {
        __syncthreads();                     // prior-phase Ds readers done
        if ((tx >> 4) == ph) {
            int cx = (tx & 15) * 4;
#pragma unroll
            for (int p = 0; p < 8; p++) {
                float4 lo, hi;
                lo.x = __uint_as_float((unsigned)acc[p][0]); hi.x = __uint_as_float((unsigned)(acc[p][0] >> 32));
                lo.y = __uint_as_float((unsigned)acc[p][1]); hi.y = __uint_as_float((unsigned)(acc[p][1] >> 32));
                lo.z = __uint_as_float((unsigned)acc[p][2]); hi.z = __uint_as_float((unsigned)(acc[p][2] >> 32));
                lo.w = __uint_as_float((unsigned)acc[p][3]); hi.w = __uint_as_float((unsigned)(acc[p][3] >> 32));
                *(float4*)(Ds + (ty * 16 + 2 * p) * DSTR + cx)     = lo;
                *(float4*)(Ds + (ty * 16 + 2 * p + 1) * DSTR + cx) = hi;
            }
        }
        __syncthreads();

        // row-scan: 2 threads/row, stride-2 over 64 cols; score = dot + nsq_j
        {
            const float* dr = Ds + myrow * DSTR + half;
            int jb = ph * 64 + half;
            float th = bS[0];
#pragma unroll 4
            for (int m = 0; m < 32; m++) {
                float s = dr[2 * m] + nsqB[jb + 2 * m];
                if (s > th) {
                    bS[0] = s; bI[0] = j0 + jb + 2 * m;
#pragma unroll
                    for (int q = 0; q < 8; q++) {
                        if (bS[q] > bS[q + 1]) {
                            float ts = bS[q]; bS[q] = bS[q + 1]; bS[q + 1] = ts;
                            int   ti = bI[q]; bI[q] = bI[q + 1]; bI[q + 1] = ti;
                        }
                    }
                    th = bS[0];
                }
            }
        }

        // col-scan (off-diag): 4 threads/col, rows qq+4m; score = dot + nsq_i
        if (!diag) {
            float cS[9]; int cI[9];
#pragma unroll
            for (int q = 0; q < 9; q++) { cS[q] = -1e30f; cI[q] = 0; }
            const float* dc = Ds + qq * DSTR + c2;
            float th2 = cS[0];
#pragma unroll 4
            for (int m = 0; m < 32; m++) {
                float s = dc[4 * m * DSTR] + nsqA[qq + 4 * m];
                if (s > th2) {
                    cS[0] = s; cI[0] = i0 + qq + 4 * m;
#pragma unroll
                    for (int q = 0; q < 8; q++) {
                        if (cS[q] > cS[q + 1]) {
                            float ts = cS[q]; cS[q] = cS[q + 1]; cS[q + 1] = ts;
                            int   ti = cI[q]; cI[q] = cI[q + 1]; cI[q + 1] = ti;
                        }
                    }
                    th2 = cS[0];
                }
            }
            // dump quarter-lists (descending) into keysC (As region)
#pragma unroll
            for (int k = 0; k < 9; k++) {
                unsigned u = __float_as_uint(cS[8 - k]);
                u = (u & 0x80000000u) ? ~u : (u | 0x80000000u);
                keysC[t * 9 + k] = ((u64)u << 32) | (unsigned)(1023 - cI[8 - k]);
            }
        }
        __syncthreads();
        if (!diag && t < 64) {
            // 4-way merge of quarter lists for col t -> g_part[node j][chunk a]
            const u64* Lc = keysC + (size_t)(4 * t) * 9;
            u64 cur[4]; int p[4];
#pragma unroll
            for (int l = 0; l < 4; l++) { cur[l] = Lc[l * 9]; p[l] = 1; }
            u64* op = g_part + ((size_t)(b * NN + j0 + ph * 64 + t) * 8 + a) * 9;
#pragma unroll
            for (int r = 0; r < 9; r++) {
                u64 m = cur[0]; int ml = 0;
#pragma unroll
                for (int l = 1; l < 4; l++) if (cur[l] > m) { m = cur[l]; ml = l; }
                op[r] = m;
                cur[ml] = (p[ml] < 9) ? Lc[ml * 9 + p[ml]] : 0ull;
                p[ml]++;
            }
        }
    }

    // row dump: keys in Ds region, 2-way merge per row -> g_part[node i][chunk bt]
    __syncthreads();
#pragma unroll
    for (int q = 0; q < 9; q++) {
        unsigned u = __float_as_uint(bS[q]);
        u = (u & 0x80000000u) ? ~u : (u | 0x80000000u);
        keysR[t * 9 + q] = ((u64)u << 32) | (unsigned)(1023 - bI[q]);
    }
    __syncthreads();
    if (t < 128) {
        const u64* L0 = keysR + (size_t)(2 * t) * 9;
        const u64* L1 = keysR + (size_t)(2 * t + 1) * 9;
        int p0 = 8, p1 = 8;
        u64* op = g_part + ((size_t)(b * NN + i0 + t) * 8 + bt) * 9;
#pragma unroll
        for (int r = 0; r < 9; r++) {
            u64 v0 = L0[p0], v1 = L1[p1];
            bool sel = v0 > v1;
            op[r] = sel ? v0 : v1;
            if (sel) p0--; else p1--;
        }
    }

    // ---- fused k3 epilogue (diagonal blocks only; As intact): Wh, f1/f2, zero den ----
    if (!diag) return;
    __syncthreads();
    float* Wc  = Bs;             // [c][h*15+f]  64*60
    float* as2 = Bs + 64 * FH;   // 120
    for (int idx = t; idx < NH * CC * FF; idx += 256) {
        int h = idx / (CC * FF); int rem2 = idx % (CC * FF);
        int c = rem2 / FF; int f = rem2 % FF;
        Wc[c * FH + h * FF + f] = Wheads[idx];
    }
    if (t < NH * 2 * FF) as2[t] = aheads[t];
    __syncthreads();
#pragma unroll
    for (int p = 0; p < 2; p++) {
        int idx = t + p * 256;               // 0..511 = 128 nodes x 4 heads
        int node = idx >> 2, h = idx & 3;
        size_t row = (size_t)b * NN + i0 + node;
        float acc2[FF];
#pragma unroll
        for (int f = 0; f < FF; f++) acc2[f] = 0.f;
#pragma unroll 8
        for (int c = 0; c < CC; c++) {
            float hc = As[c * 128 + node];
#pragma unroll
            for (int f = 0; f < FF; f++) acc2[f] = fmaf(hc, Wc[c * FH + h * FF + f], acc2[f]);
        }
        float* wout = g_Wh + row * FH + h * FF;
#pragma unroll
        for (int f = 0; f < FF; f++) wout[f] = acc2[f];
        float f1 = 0.f, f2 = 0.f;
#pragma unroll
        for (int f = 0; f < FF; f++) {
            f1 = fmaf(acc2[f], as2[h * 2 * FF + f], f1);
            f2 = fmaf(acc2[f], as2[h * 2 * FF + FF + f], f2);
        }
        g_f1[row * NH + h] = f1;
        g_f2[row * NH + h] = f2;
        g_den[row * NH + h] = 0.f;
    }
}

// ---------------- K2b: 8-way merge of sorted chunk lists -> g_idx ----------------
__global__ void k_mergetop() {
    int row = blockIdx.x * 256 + threadIdx.x;        // [0, B*N)
    const u64* L = g_part + (size_t)row * 72;
    u64 cur[8]; int p[8];
#pragma unroll
    for (int l = 0; l < 8; l++) { cur[l] = L[l * 9]; p[l] = 1; }
    int* op = g_idx + (size_t)row * 9;
#pragma unroll
    for (int r = 0; r < 9; r++) {
        u64 m = cur[0]; int ml = 0;
#pragma unroll
        for (int l = 1; l < 8; l++) if (cur[l] > m) { m = cur[l]; ml = l; }
        op[r] = 1023 - (int)(m & 0xFFFFFFFFull);
        cur[ml] = (p[ml] < 9) ? L[ml * 9 + p[ml]] : 0ull;
        p[ml]++;
    }
}

// ---------------- K4: denominators (heads) + exp cache — edge-parallel ----------------
__global__ void k4() {
    int e = blockIdx.x * 256 + threadIdx.x;          // [0, B*N*K)
    int row = e / 9;
    int bbase = row & ~1023;
    int jr = bbase + g_idx[e];
    float4 f1v = *(const float4*)(g_f1 + (size_t)row * 4);
    float4 f2v = *(const float4*)(g_f2 + (size_t)jr * 4);
    float* dp = g_den + (size_t)jr * 4;
    float e0 = f1v.x + f2v.x; e0 = e0 > 0.f ? e0 : ALPHA * e0;
    float e1 = f1v.y + f2v.y; e1 = e1 > 0.f ? e1 : ALPHA * e1;
    float e2 = f1v.z + f2v.z; e2 = e2 > 0.f ? e2 : ALPHA * e2;
    float e3 = f1v.w + f2v.w; e3 = e3 > 0.f ? e3 : ALPHA * e3;
    float x0 = __expf(e0), x1 = __expf(e1), x2 = __expf(e2), x3 = __expf(e3);
    *(float4*)(g_ew + (size_t)e * 4) = make_float4(x0, x1, x2, x3);
    atomicAdd(dp + 0, x0);
    atomicAdd(dp + 1, x1);
    atomicAdd(dp + 2, x2);
    atomicAdd(dp + 3, x3);
}

// ---------------- K5: head aggregation + ELU -> hcat ----------------
__global__ void k5() {
    __shared__ float ws[4 * KK * NH];
    __shared__ int   js[4 * KK];
    int t = threadIdx.x;                 // 240 = 4 nodes x 60
    int row0 = blockIdx.x * 4;
    int bbase = row0 & ~1023;
    if (t < 4 * KK * NH) {
        int local = t / (KK * NH), rem = t % (KK * NH);
        int k = rem >> 2, h = rem & 3;
        int row = row0 + local;
        int jr = bbase + g_idx[row * 9 + k];
        ws[t] = __fdividef(g_ew[((size_t)row * 9 + k) * 4 + h], g_den[(size_t)jr * 4 + h]);
        if (h == 0) js[local * KK + k] = jr;
    }
    __syncthreads();
    int local = t / FH, c = t % FH;
    int row = row0 + local;
    int h = c / FF;
    float acc = 0.f;
#pragma unroll
    for (int k = 0; k < KK; k++)
        acc = fmaf(ws[(local * KK + k) * 4 + h], g_Wh[(size_t)js[local * KK + k] * FH + c], acc);
    g_hcat[(size_t)row * FH + c] = acc > 0.f ? acc : expm1f(acc);
}

// ---------------- K6: W_out GEMM + f1o/f2o, zero deno ----------------
__global__ __launch_bounds__(256) void k6(const float* __restrict__ Wout,
                                          const float* __restrict__ aout) {
    __shared__ float Hc[64 * 61];        // [node][c]
    __shared__ float Wo[FH * CC];
    __shared__ float av[2 * CC];
    int t = threadIdx.x;
    int b = blockIdx.x >> 4;
    int n0 = (blockIdx.x & 15) * 64;
    for (int idx = t; idx < FH * CC; idx += 256) Wo[idx] = Wout[idx];
    if (t < 2 * CC) av[t] = aout[t];
    for (int idx = t; idx < 64 * FH; idx += 256) {
        int node = idx / FH, c = idx % FH;
        Hc[node * 61 + c] = g_hcat[((size_t)(b * NN + n0 + node)) * FH + c];
    }
    __syncthreads();
    int node = t >> 2, q = t & 3;
    size_t row = (size_t)b * NN + n0 + node;
    float acc[16];
#pragma unroll
    for (int f = 0; f < 16; f++) acc[f] = 0.f;
#pragma unroll 6
    for (int c = 0; c < FH; c++) {
        float hv = Hc[node * 61 + c];
#pragma unroll
        for (int f = 0; f < 16; f++)
            acc[f] = fmaf(hv, Wo[c * CC + q * 16 + f], acc[f]);
    }
    float4* wout4 = (float4*)(g_Who + row * CC + q * 16);
#pragma unroll
    for (int p = 0; p < 4; p++)
        wout4[p] = make_float4(acc[4 * p], acc[4 * p + 1], acc[4 * p + 2], acc[4 * p + 3]);
    float f1 = 0.f, f2 = 0.f;
#pragma unroll
    for (int f = 0; f < 16; f++) {
        f1 = fmaf(acc[f], av[q * 16 + f], f1);
        f2 = fmaf(acc[f], av[CC + q * 16 + f], f2);
    }
#pragma unroll
    for (int off = 1; off < 4; off <<= 1) {
        f1 += __shfl_xor_sync(0xFFFFFFFFu, f1, off);
        f2 += __shfl_xor_sync(0xFFFFFFFFu, f2, off);
    }
    if (q == 0) {
        g_f1o[row] = f1;
        g_f2o[row] = f2;
        g_deno[row] = 0.f;
    }
}

// ---------------- K7: output-layer denominators + exp cache — edge-parallel ----------------
__global__ void k7() {
    int e = blockIdx.x * 256 + threadIdx.x;          // [0, B*N*K)
    int row = e / 9;
    int bbase = row & ~1023;
    int jr = bbase + g_idx[e];
    float ee = g_f1o[row] + g_f2o[jr];
    ee = ee > 0.f ? ee : ALPHA * ee;
    float ex = __expf(ee);
    g_ewo[e] = ex;
    atomicAdd(g_deno + jr, ex);
}

// ---------------- K8: out-aggregate + ELU + LReLU + conv1x1 + BN + residual ----------------
__global__ void k8(const float* __restrict__ x, const float* __restrict__ cw,
                   const float* __restrict__ cb, const float* __restrict__ gamma,
                   const float* __restrict__ beta, float* __restrict__ out) {
    __shared__ float cws[CC * 65];
    __shared__ float ys[32 * 65];
    __shared__ float ws[32 * KK];
    __shared__ int   js[32 * KK];
    int t = threadIdx.x;
    int b = blockIdx.x >> 5;
    int n0 = (blockIdx.x & 31) * 32;
    for (int idx = t; idx < CC * CC; idx += 256) {
        int o = idx >> 6, c = idx & 63;
        cws[o * 65 + c] = cw[idx];
    }
    for (int idx = t; idx < 32 * KK; idx += 256) {
        int node = idx / KK, k = idx % KK;
        int row = b * NN + n0 + node;
        int jr = b * NN + g_idx[row * 9 + k];
        ws[idx] = __fdividef(g_ewo[(size_t)row * 9 + k], g_deno[jr]);
        js[idx] = jr;
    }
    __syncthreads();
#pragma unroll
    for (int p = 0; p < 8; p++) {
        int idx = t + p * 256;
        int node = idx >> 6, c = idx & 63;
        float acc = 0.f;
#pragma unroll
        for (int k = 0; k < KK; k++)
            acc = fmaf(ws[node * KK + k], g_Who[(size_t)js[node * KK + k] * CC + c], acc);
        float e = acc > 0.f ? acc : expm1f(acc);     // ELU
        ys[node * 65 + c] = e > 0.f ? e : 0.01f * e; // LeakyReLU(0.01)
    }
    __syncthreads();
    int node = t & 31, og = t >> 5;
    float bnr = 1.0f / sqrtf(1.0f + 1e-5f);
#pragma unroll
    for (int p = 0; p < 8; p++) {
        int o = og * 8 + p;
        float s = cb[o];
        const float* yr = ys + node * 65;
        const float* cr = cws + o * 65;
#pragma unroll
        for (int c = 0; c < CC; c++) s = fmaf(cr[c], yr[c], s);
        s = s * bnr * gamma[o] + beta[o];
        size_t oidx = ((size_t)(b * CC + o)) * NN + n0 + node;
        out[oidx] = s + x[oidx];
    }
}

// ---------------- launch ----------------
extern "C" void kernel_launch(void* const* d_in, const int* in_sizes, int n_in,
                              void* d_out, int out_size) {
    const float* x      = (const float*)d_in[0];
    const float* Wheads = (const float*)d_in[1];
    const float* aheads = (const float*)d_in[2];
    const float* Wout   = (const float*)d_in[3];
    const float* aout   = (const float*)d_in[4];
    const float* convw  = (const float*)d_in[5];
    const float* convb  = (const float*)d_in[6];
    const float* gamma  = (const float*)d_in[7];
    const float* beta   = (const float*)d_in[8];
    float* out = (float*)d_out;

    const int GT_SMEM = (2 * 64 * 128 + 128 * DSTR + 256) * 4;  // 101376B
    static bool attr_set = false;
    if (!attr_set) {
        cudaFuncSetAttribute(k_gramtop, cudaFuncAttributeMaxDynamicSharedMemorySize, GT_SMEM);
        attr_set = true;
    }

    k_norm<<<2 * BB * NN / 256, 256>>>(x);       // launch 0
    k_dummy<<<1, 32>>>();                        // launch 1
    k_dummy<<<1, 32>>>();                        // launch 2
    k_gramtop<<<dim3(36, BB), 256, GT_SMEM>>>(Wheads, aheads);  // launch 3 (profiled)
    k_mergetop<<<BB * NN / 256, 256>>>();
    k4<<<BB * NN * KK / 256, 256>>>();
    k5<<<BB * NN / 4, 240>>>();
    k6<<<BB * 16, 256>>>(Wout, aout);
    k7<<<BB * NN * KK / 256, 256>>>();
    k8<<<BB * 32, 256>>>(x, convw, convb, gamma, beta, out);
}